// round 14
// baseline (speedup 1.0000x reference)
#include <cuda_runtime.h>
#include <cuda_fp16.h>
#include <math.h>
#include <stdint.h>

#define G 4
#define NNODE 1024
#define FDIM 256
#define HDIM 256
#define BATCH 32
#define LAYERS 4
#define NCTA 128
#define NTHR 512

// ---------------- scratch (device globals; no allocation allowed) -----------
__device__ __half g_ah [G * NNODE * NNODE];          // adjacency, half, x1024
__device__ __half g_xin[G * NNODE * FDIM];           // input feats, half
__device__ __half g_wh [(1 + LAYERS) * HDIM * HDIM]; // weights, half
__device__ __half g_h0h[G * NNODE * HDIM];           // h0 half (residual + layer0 in)
__device__ __half g_xh [G * NNODE * HDIM];           // hidden activations (half)
__device__ float  g_tp0[G * NNODE * HDIM];           // A@x split-K partial 0 (x1024)
__device__ float  g_tp1[G * NNODE * HDIM];           // A@x split-K partial 1 (x1024)
__device__ float  g_xl [G * NNODE * HDIM];           // final output fp32
__device__ float  g_part[BATCH * 8 * HDIM];          // reduce partials
__device__ float  g_cnt [BATCH * 8];                 // reduce counts
__device__ unsigned g_bar_epoch;
__device__ unsigned g_bar_count;

// ---------------- smem layout ------------------------------------------------
#define STR144 144                        // 64-half rows + pad  (16 mod 128)
#define STR272 272                        // 128-half rows + pad (16 mod 128)
#define POOL 512
// h0 gemm (BM128 BN64 BK64, 3 stages):
#define H_A_STG (128 * STR144)            // 18432
#define H_B_STG (64 * STR144)             // 9216
#define H_OFF_B (POOL + 3 * H_A_STG)
// ax gemm (BM128 BN128 BK64, 3 stages):
#define X_A_STG (128 * STR144)            // 18432
#define X_B_STG (64 * STR272)             // 17408
#define X_OFF_B (POOL + 3 * X_A_STG)
// dense-from-tp (BM128 BN64 BK128, 2 chunks):
#define D_T_STG (128 * STR272)            // 34816
#define D_W_STG (128 * STR144)            // 18432
#define D_OFF_W (POOL + 2 * D_T_STG)
#define SMEM_BYTES (POOL + 3 * X_A_STG + 3 * X_B_STG)   // 108032 (max of all)

__device__ __forceinline__ uint32_t smem_u32(const void* p) {
    uint32_t a;
    asm("{ .reg .u64 t; cvta.to.shared.u64 t, %1; cvt.u32.u64 %0, t; }" : "=r"(a) : "l"(p));
    return a;
}
__device__ __forceinline__ void cpa16(uint32_t dst, const void* src) {
    asm volatile("cp.async.cg.shared.global [%0], [%1], 16;" :: "r"(dst), "l"(src));
}
#define CP_COMMIT() asm volatile("cp.async.commit_group;" ::: "memory")
#define CP_WAIT1()  asm volatile("cp.async.wait_group 1;" ::: "memory")
#define CP_WAIT0()  asm volatile("cp.async.wait_group 0;" ::: "memory")

__device__ __forceinline__ void ldsm_x4(uint32_t* r, uint32_t addr) {
    asm volatile("ldmatrix.sync.aligned.m8n8.x4.shared.b16 {%0,%1,%2,%3}, [%4];"
        : "=r"(r[0]), "=r"(r[1]), "=r"(r[2]), "=r"(r[3]) : "r"(addr));
}
__device__ __forceinline__ void ldsm_x4_t(uint32_t* r, uint32_t addr) {
    asm volatile("ldmatrix.sync.aligned.m8n8.x4.trans.shared.b16 {%0,%1,%2,%3}, [%4];"
        : "=r"(r[0]), "=r"(r[1]), "=r"(r[2]), "=r"(r[3]) : "r"(addr));
}
__device__ __forceinline__ void mma_f16(float* d, const uint32_t* a, uint32_t b0, uint32_t b1) {
    asm volatile(
        "mma.sync.aligned.m16n8k16.row.col.f32.f16.f16.f32 "
        "{%0,%1,%2,%3}, {%4,%5,%6,%7}, {%8,%9}, {%0,%1,%2,%3};"
        : "+f"(d[0]), "+f"(d[1]), "+f"(d[2]), "+f"(d[3])
        : "r"(a[0]), "r"(a[1]), "r"(a[2]), "r"(a[3]), "r"(b0), "r"(b1));
}

// ---------------- device-wide barrier (128 CTAs, 1/SM) ----------------------
__device__ __forceinline__ void grid_barrier(unsigned target) {
    __syncthreads();
    if (threadIdx.x == 0) {
        __threadfence();
        unsigned old = atomicAdd(&g_bar_count, 1u);
        if (old == NCTA - 1) {
            atomicExch(&g_bar_count, 0u);
            __threadfence();
            atomicAdd(&g_bar_epoch, 1u);
        } else {
            unsigned e;
            do {
                asm volatile("ld.acquire.gpu.u32 %0, [%1];"
                             : "=r"(e) : "l"(&g_bar_epoch));
                if ((int)(e - target) >= 0) break;
                __nanosleep(32);
            } while (true);
        }
    }
    __syncthreads();
}

// ---------------- h0 dense: C = relu(A@B + bias), BM128/BN64/BK64 ------------
__device__ void h0_gemm(char* smraw, const __half* A, const __half* B,
                        const float* bias, __half* Ch, int bx, int by) {
    float* sbias = (float*)smraw;
    const uint32_t uA = smem_u32(smraw + POOL);
    const uint32_t uB = smem_u32(smraw + H_OFF_B);
    const int tid = threadIdx.x, wid = tid >> 5, lane = tid & 31;
    const int wm = wid >> 2, wn = wid & 3;
    const int gid = lane >> 2, tig = lane & 3;
    const int l15 = lane & 15, l4 = lane >> 4;

    A += (long)(by * 128) * FDIM;
    B += (long)bx * 64;
    if (tid < 64) sbias[tid] = bias[bx * 64 + tid];

    auto load_stage = [&](int c, int s) {
        const __half* Ag = A + c * 64;
        const __half* Bg = B + (long)(c * 64) * HDIM;
        uint32_t aB = uA + s * H_A_STG, bB = uB + s * H_B_STG;
        #pragma unroll
        for (int i = 0; i < 2; i++) {
            int idx = tid + i * NTHR;
            int r = idx >> 3, q = idx & 7;
            cpa16(aB + r * STR144 + q * 16, Ag + (long)r * FDIM + q * 8);
        }
        {
            int r = tid >> 3, q = tid & 7;
            cpa16(bB + r * STR144 + q * 16, Bg + (long)r * HDIM + q * 8);
        }
    };
    const uint32_t aLane = (uint32_t)((wm * 32 + l15) * STR144 + l4 * 16);
    const uint32_t bLane = (uint32_t)(l15 * STR144 + (wn * 16 + l4 * 8) * 2);

    float d[2][2][4] = {};
    load_stage(0, 0); CP_COMMIT();
    load_stage(1, 1); CP_COMMIT();
    for (int c = 0; c < 4; c++) {
        CP_WAIT1();
        __syncthreads();
        if (c + 2 < 4) load_stage(c + 2, (c + 2) % 3);
        CP_COMMIT();
        const uint32_t aS = uA + (c % 3) * H_A_STG + aLane;
        const uint32_t bS = uB + (c % 3) * H_B_STG + bLane;
        uint32_t a0[2][4], a1[2][4], bp[2][4];
        ldsm_x4(a0[0], aS);
        ldsm_x4(a1[0], aS + 16 * STR144);
        ldsm_x4_t(bp[0], bS);
        #pragma unroll
        for (int ks = 0; ks < 4; ks++) {
            const int cu = ks & 1, nx = cu ^ 1;
            if (ks < 3) {
                ldsm_x4(a0[nx], aS + (ks + 1) * 32);
                ldsm_x4(a1[nx], aS + (ks + 1) * 32 + 16 * STR144);
                ldsm_x4_t(bp[nx], bS + (ks + 1) * 16 * STR144);
            }
            mma_f16(d[0][0], a0[cu], bp[cu][0], bp[cu][1]);
            mma_f16(d[1][0], a1[cu], bp[cu][0], bp[cu][1]);
            mma_f16(d[0][1], a0[cu], bp[cu][2], bp[cu][3]);
            mma_f16(d[1][1], a1[cu], bp[cu][2], bp[cu][3]);
        }
    }
    CP_WAIT0();
    #pragma unroll
    for (int mt = 0; mt < 2; mt++)
        #pragma unroll
        for (int hf = 0; hf < 2; hf++) {
            const long row = (long)by * 128 + wm * 32 + mt * 16 + hf * 8 + gid;
            #pragma unroll
            for (int nt = 0; nt < 2; nt++) {
                const int cl = wn * 16 + nt * 8 + 2 * tig;
                float v0 = fmaxf(d[mt][nt][hf * 2 + 0] + sbias[cl], 0.0f);
                float v1 = fmaxf(d[mt][nt][hf * 2 + 1] + sbias[cl + 1], 0.0f);
                *(__half2*)(Ch + row * HDIM + bx * 64 + cl) = __floats2half2_rn(v0, v1);
            }
        }
}

// ---------------- A@x split-K: partial = A[128 rows]@x[K=512], BN=128 --------
__device__ void ax_gemm(char* smraw, const __half* A, const __half* X,
                        float* tp, int bx, int by) {
    const uint32_t uA = smem_u32(smraw + POOL);
    const uint32_t uB = smem_u32(smraw + X_OFF_B);
    const int tid = threadIdx.x, wid = tid >> 5, lane = tid & 31;
    const int wm = wid >> 2, wn = wid & 3;          // 4x4 warps, warp 32x32
    const int gid = lane >> 2, tig = lane & 3;
    const int l15 = lane & 15, l4 = lane >> 4;

    auto load_stage = [&](int c, int s) {
        uint32_t aB = uA + s * X_A_STG, bB = uB + s * X_B_STG;
        #pragma unroll
        for (int i = 0; i < 2; i++) {               // A: 128 rows x 8 x 16B
            int idx = tid + i * NTHR;
            int r = idx >> 3, q = idx & 7;
            cpa16(aB + r * STR144 + q * 16,
                  A + ((long)(by * 128 + r)) * NNODE + c * 64 + q * 8);
        }
        #pragma unroll
        for (int i = 0; i < 2; i++) {               // B: 64 rows x 16 x 16B
            int idx = tid + i * NTHR;
            int r = idx >> 4, q = idx & 15;
            cpa16(bB + r * STR272 + q * 16,
                  X + ((long)(c * 64 + r)) * HDIM + bx * 128 + q * 8);
        }
    };
    const uint32_t aLane = (uint32_t)((wm * 32 + l15) * STR144 + l4 * 16);
    const uint32_t bLane = (uint32_t)(l15 * STR272 + (wn * 32 + l4 * 8) * 2);

    float d[2][4][4] = {};
    load_stage(0, 0); CP_COMMIT();
    load_stage(1, 1); CP_COMMIT();
    for (int c = 0; c < 8; c++) {
        CP_WAIT1();
        __syncthreads();
        if (c + 2 < 8) load_stage(c + 2, (c + 2) % 3);
        CP_COMMIT();
        const uint32_t aS = uA + (c % 3) * X_A_STG + aLane;
        const uint32_t bS = uB + (c % 3) * X_B_STG + bLane;
        uint32_t a0[2][4], a1[2][4], bp0[2][4], bp1[2][4];
        ldsm_x4(a0[0], aS);
        ldsm_x4(a1[0], aS + 16 * STR144);
        ldsm_x4_t(bp0[0], bS);
        ldsm_x4_t(bp1[0], bS + 32);
        #pragma unroll
        for (int ks = 0; ks < 4; ks++) {
            const int cu = ks & 1, nx = cu ^ 1;
            if (ks < 3) {
                ldsm_x4(a0[nx], aS + (ks + 1) * 32);
                ldsm_x4(a1[nx], aS + (ks + 1) * 32 + 16 * STR144);
                ldsm_x4_t(bp0[nx], bS + (ks + 1) * 16 * STR272);
                ldsm_x4_t(bp1[nx], bS + (ks + 1) * 16 * STR272 + 32);
            }
            mma_f16(d[0][0], a0[cu], bp0[cu][0], bp0[cu][1]);
            mma_f16(d[1][0], a1[cu], bp0[cu][0], bp0[cu][1]);
            mma_f16(d[0][1], a0[cu], bp0[cu][2], bp0[cu][3]);
            mma_f16(d[1][1], a1[cu], bp0[cu][2], bp0[cu][3]);
            mma_f16(d[0][2], a0[cu], bp1[cu][0], bp1[cu][1]);
            mma_f16(d[1][2], a1[cu], bp1[cu][0], bp1[cu][1]);
            mma_f16(d[0][3], a0[cu], bp1[cu][2], bp1[cu][3]);
            mma_f16(d[1][3], a1[cu], bp1[cu][2], bp1[cu][3]);
        }
    }
    CP_WAIT0();
    #pragma unroll
    for (int mt = 0; mt < 2; mt++)
        #pragma unroll
        for (int hf = 0; hf < 2; hf++) {
            const long row = (long)by * 128 + wm * 32 + mt * 16 + hf * 8 + gid;
            #pragma unroll
            for (int nt = 0; nt < 4; nt++) {
                const int cl = wn * 32 + nt * 8 + 2 * tig;
                *(float2*)(tp + row * HDIM + bx * 128 + cl) =
                    make_float2(d[mt][nt][hf * 2 + 0], d[mt][nt][hf * 2 + 1]);
            }
        }
}

// ---------------- dense from tp partials: act((tp0+tp1)/1024 @ W + b) --------
// BM128/BN64/BK128, 2 chunks. ACT 1 relu, 2 tanh. MODE 0 half, 2 fp32.
template <int ACT, int MODE>
__device__ void dense_tp(char* smraw, const float* tp0, const float* tp1,
                         const __half* W, const float* bias,
                         __half* Ch, float* Cf, int bx, int by) {
    float* sbias = (float*)smraw;
    char* sT = smraw + POOL;
    const uint32_t uT = smem_u32(sT);
    const uint32_t uW = smem_u32(smraw + D_OFF_W);
    const int tid = threadIdx.x, wid = tid >> 5, lane = tid & 31;
    const int wm = wid >> 2, wn = wid & 3;
    const int gid = lane >> 2, tig = lane & 3;
    const int l15 = lane & 15, l4 = lane >> 4;
    const float inv = 1.0f / 1024.0f;

    if (tid < 64) sbias[tid] = bias[bx * 64 + tid];

    // prefetch both W stages (K=256 -> 2 chunks of 128)
    #pragma unroll
    for (int c = 0; c < 2; c++) {
        uint32_t wB = uW + c * D_W_STG;
        const __half* Wg = W + (long)(c * 128) * HDIM + bx * 64;
        #pragma unroll
        for (int i = 0; i < 2; i++) {
            int idx = tid + i * NTHR;
            int r = idx >> 3, q = idx & 7;
            cpa16(wB + r * STR144 + q * 16, Wg + (long)r * HDIM + q * 8);
        }
        CP_COMMIT();
    }

    const uint32_t aLane = (uint32_t)((wm * 32 + l15) * STR272 + l4 * 16);
    const uint32_t bLane = (uint32_t)(l15 * STR144 + (wn * 16 + l4 * 8) * 2);

    float d[2][2][4] = {};
    for (int c = 0; c < 2; c++) {
        // manual t tile: (tp0+tp1)*inv -> half -> smem buffer c
        char* tbuf = sT + c * D_T_STG;
        #pragma unroll
        for (int i = 0; i < 4; i++) {
            int idx = tid + i * NTHR;
            int r = idx >> 4, q = idx & 15;
            long base = ((long)(by * 128 + r)) * HDIM + c * 128 + q * 8;
            float4 p0a = *(const float4*)(tp0 + base);
            float4 p0b = *(const float4*)(tp0 + base + 4);
            float4 p1a = *(const float4*)(tp1 + base);
            float4 p1b = *(const float4*)(tp1 + base + 4);
            __half2 h[4];
            h[0] = __floats2half2_rn((p0a.x + p1a.x) * inv, (p0a.y + p1a.y) * inv);
            h[1] = __floats2half2_rn((p0a.z + p1a.z) * inv, (p0a.w + p1a.w) * inv);
            h[2] = __floats2half2_rn((p0b.x + p1b.x) * inv, (p0b.y + p1b.y) * inv);
            h[3] = __floats2half2_rn((p0b.z + p1b.z) * inv, (p0b.w + p1b.w) * inv);
            *(uint4*)(tbuf + r * STR272 + q * 16) = *(uint4*)h;
        }
        if (c == 0) CP_WAIT1(); else CP_WAIT0();
        __syncthreads();

        const uint32_t aS = uT + c * D_T_STG + aLane;
        const uint32_t bS = uW + c * D_W_STG + bLane;
        uint32_t a0[2][4], a1[2][4], bp[2][4];
        ldsm_x4(a0[0], aS);
        ldsm_x4(a1[0], aS + 16 * STR272);
        ldsm_x4_t(bp[0], bS);
        #pragma unroll
        for (int ks = 0; ks < 8; ks++) {
            const int cu = ks & 1, nx = cu ^ 1;
            if (ks < 7) {
                ldsm_x4(a0[nx], aS + (ks + 1) * 32);
                ldsm_x4(a1[nx], aS + (ks + 1) * 32 + 16 * STR272);
                ldsm_x4_t(bp[nx], bS + (ks + 1) * 16 * STR144);
            }
            mma_f16(d[0][0], a0[cu], bp[cu][0], bp[cu][1]);
            mma_f16(d[1][0], a1[cu], bp[cu][0], bp[cu][1]);
            mma_f16(d[0][1], a0[cu], bp[cu][2], bp[cu][3]);
            mma_f16(d[1][1], a1[cu], bp[cu][2], bp[cu][3]);
        }
        __syncthreads();
    }

    #pragma unroll
    for (int mt = 0; mt < 2; mt++)
        #pragma unroll
        for (int hf = 0; hf < 2; hf++) {
            const long row = (long)by * 128 + wm * 32 + mt * 16 + hf * 8 + gid;
            const long rc = row * HDIM + bx * 64;
            #pragma unroll
            for (int nt = 0; nt < 2; nt++) {
                const int cl = wn * 16 + nt * 8 + 2 * tig;
                float v0 = d[mt][nt][hf * 2 + 0] + sbias[cl];
                float v1 = d[mt][nt][hf * 2 + 1] + sbias[cl + 1];
                if (ACT == 1) { v0 = fmaxf(v0, 0.0f); v1 = fmaxf(v1, 0.0f); }
                if (ACT == 2) { v0 = tanhf(v0); v1 = tanhf(v1); }
                if (MODE == 0)
                    *(__half2*)(Ch + rc + cl) = __floats2half2_rn(v0, v1);
                else
                    *(float2*)(Cf + rc + cl) = make_float2(v0, v1);
            }
        }
}

// ---------------- the megakernel --------------------------------------------
#define TOT4_A (G * NNODE * NNODE / 4)
#define TOT4_X (G * NNODE * FDIM / 4)
#define TOT4_W ((1 + LAYERS) * HDIM * HDIM / 4)
#define TOT4_WIN (FDIM * HDIM / 4)
#define A_SLICE (TOT4_A / NCTA)               // 8192 float4 per CTA

__global__ void __launch_bounds__(NTHR, 1)
meganet(const float* batch_xs, const float* batch_as,
        const float* w_in, const float* b_in,
        const float* gcn_w, const float* gcn_b,
        const int* gidx, const int* mask, float* out) {
    extern __shared__ char smraw[];
    const int cta = blockIdx.x;
    const int tid = threadIdx.x;
    unsigned bt = g_bar_epoch;

    // ---- phase P: convert X + W ----
    {
        const float4* x4 = (const float4*)batch_xs;
        const float4* wi = (const float4*)w_in;
        const float4* gw = (const float4*)gcn_w;
        __half2* xh2 = (__half2*)g_xin;
        __half2* wh2 = (__half2*)g_wh;
        const int total = TOT4_X + TOT4_W;
        for (int i = cta * NTHR + tid; i < total; i += NCTA * NTHR) {
            float4 v; __half2* dst;
            if (i < TOT4_X) { v = x4[i]; dst = xh2 + 2 * i; }
            else {
                int j = i - TOT4_X;
                if (j < TOT4_WIN) { v = wi[j]; dst = wh2 + 2 * j; }
                else { v = gw[j - TOT4_WIN]; dst = wh2 + 2 * j; }
            }
            dst[0] = __floats2half2_rn(v.x, v.y);
            dst[1] = __floats2half2_rn(v.z, v.w);
        }
    }
    grid_barrier(++bt);

    // ---- phase 0: h0 = relu(X @ w_in + b); then convert A slice ----
    h0_gemm(smraw, g_xin, g_wh, b_in, g_h0h, cta & 3, cta >> 2);
    {
        const float4* a4 = (const float4*)batch_as + (long)cta * A_SLICE;
        __half2* ah2 = (__half2*)g_ah + (long)cta * A_SLICE * 2;
        #pragma unroll 4
        for (int i = tid; i < A_SLICE; i += NTHR) {
            float4 v = a4[i];
            ah2[2 * i + 0] = __floats2half2_rn(v.x * 1024.0f, v.y * 1024.0f);
            ah2[2 * i + 1] = __floats2half2_rn(v.z * 1024.0f, v.w * 1024.0f);
        }
    }
    grid_barrier(++bt);

    // ---- fused GCN layers: split-K A@x then dense-from-partials ----
    const __half* cur = g_h0h;
    for (int i = 0; i < LAYERS; i++) {
        {   // A@x split-K: bx(2) x by(8) x kh(2) x g(4) = 128 CTAs
            const int bx = cta & 1, by = (cta >> 1) & 7;
            const int kh = (cta >> 4) & 1, g = cta >> 5;
            const __half* A = g_ah + (long)g * NNODE * NNODE + (long)kh * 512;
            const __half* X = cur + (long)g * NNODE * HDIM + (long)kh * 512 * HDIM;
            float* tp = (kh ? g_tp1 : g_tp0) + (long)g * NNODE * HDIM;
            ax_gemm(smraw, A, X, tp, bx, by);
        }
        grid_barrier(++bt);
        if (i < LAYERS - 1) {
            dense_tp<1, 0>(smraw, g_tp0, g_tp1,
                           g_wh + (size_t)(1 + i) * HDIM * HDIM, gcn_b + i * HDIM,
                           g_xh, nullptr, cta & 3, cta >> 2);
            cur = g_xh;
        } else {
            dense_tp<2, 2>(smraw, g_tp0, g_tp1,
                           g_wh + (size_t)LAYERS * HDIM * HDIM,
                           gcn_b + (LAYERS - 1) * HDIM,
                           nullptr, g_xl, cta & 3, cta >> 2);
        }
        grid_barrier(++bt);
    }

    // ---- phase R1: partial masked sums ----
    {
        const int b = cta >> 2;
        const int s = ((cta & 3) << 1) + (tid >> 8);
        const int h = tid & 255;
        const int g = gidx[b];
        const float* xb = g_xl  + (size_t)g * NNODE * HDIM;
        const __half* rb = g_h0h + (size_t)g * NNODE * HDIM;
        const int* mb = mask + b * NNODE;
        float acc = 0.0f, cnt = 0.0f;
        #pragma unroll 4
        for (int n = s * 128; n < s * 128 + 128; n++) {
            float m = (mb[n] != 0) ? 1.0f : 0.0f;
            cnt += m;
            acc += m * (xb[(size_t)n * HDIM + h] +
                        __half2float(rb[(size_t)n * HDIM + h]));
        }
        g_part[(b * 8 + s) * HDIM + h] = acc;
        if (h == 0) g_cnt[b * 8 + s] = cnt;
    }
    grid_barrier(++bt);

    // ---- phase R2: combine (32 CTAs, first 256 threads) ----
    if (cta < BATCH && tid < HDIM) {
        const int b = cta, h = tid;
        float acc = 0.0f, cnt = 0.0f;
        #pragma unroll
        for (int s = 0; s < 8; s++) {
            acc += g_part[(b * 8 + s) * HDIM + h];
            cnt += g_cnt[b * 8 + s];
        }
        out[b * HDIM + h] = acc / fmaxf(cnt, 1.0f);
    }
}

// ---------------- launch -----------------------------------------------------
extern "C" void kernel_launch(void* const* d_in, const int* in_sizes, int n_in,
                              void* d_out, int out_size) {
    const float* batch_xs = (const float*)d_in[0];
    const float* batch_as = (const float*)d_in[1];
    const float* w_in     = (const float*)d_in[2];
    const float* b_in     = (const float*)d_in[3];
    const float* gcn_w    = (const float*)d_in[4];
    const float* gcn_b    = (const float*)d_in[5];
    const int*   gidx     = (const int*)d_in[6];
    const int*   cp_mask  = (const int*)d_in[7];
    float* out = (float*)d_out;

    cudaFuncSetAttribute(meganet, cudaFuncAttributeMaxDynamicSharedMemorySize,
                         SMEM_BYTES);

    meganet<<<NCTA, NTHR, SMEM_BYTES>>>(batch_xs, batch_as, w_in, b_in,
                                        gcn_w, gcn_b, gidx, cp_mask, out);
}

// round 15
// speedup vs baseline: 1.0266x; 1.0266x over previous
#include <cuda_runtime.h>
#include <cuda_fp16.h>
#include <math.h>
#include <stdint.h>

#define G 4
#define NNODE 1024
#define FDIM 256
#define HDIM 256
#define BATCH 32
#define LAYERS 4
#define NCTA 128
#define NTHR 512

// ---------------- scratch (device globals; no allocation allowed) -----------
__device__ __half g_ah [G * NNODE * NNODE];          // adjacency, half, x1024
__device__ __half g_xin[G * NNODE * FDIM];           // input feats, half
__device__ __half g_wh [(1 + LAYERS) * HDIM * HDIM]; // weights, half
__device__ __half g_h0h[G * NNODE * HDIM];           // h0 half (residual + layer0 in)
__device__ __half g_th [G * NNODE * HDIM];           // A @ x (half)
__device__ __half g_xh [G * NNODE * HDIM];           // hidden activations (half)
__device__ float  g_xl [G * NNODE * HDIM];           // final output fp32
__device__ float  g_part[BATCH * 8 * HDIM];          // reduce partials
__device__ float  g_cnt [BATCH * 8];                 // reduce counts
__device__ unsigned g_bar_epoch;                     // barrier epoch (monotone)
__device__ unsigned g_bar_count;                     // barrier arrive counter

// ---------------- tiling (R10 champion config) -------------------------------
// CTA tile 128(M) x 64(N), warps 4(M) x 4(N), warp tile 32x16. 1 CTA/SM.
#define BM 128
#define BN 64
#define BK 64
#define NSTAGE 4
#define PFD 3
#define ASTR_B 144                        // A chunk row stride bytes
#define BSTR_B 144                        // B chunk row stride bytes
#define A_STG_B (BM * ASTR_B)             // 18432 B
#define B_STG_B (BK * BSTR_B)             // 9216 B
#define SM_BIAS_B 512
#define SMEM_BYTES (SM_BIAS_B + NSTAGE * (A_STG_B + B_STG_B))   // 111104 B

__device__ __forceinline__ uint32_t smem_u32(const void* p) {
    uint32_t a;
    asm("{ .reg .u64 t; cvta.to.shared.u64 t, %1; cvt.u32.u64 %0, t; }" : "=r"(a) : "l"(p));
    return a;
}
__device__ __forceinline__ void cpa16(uint32_t dst, const void* src) {
    asm volatile("cp.async.cg.shared.global [%0], [%1], 16;" :: "r"(dst), "l"(src));
}
#define CP_COMMIT() asm volatile("cp.async.commit_group;" ::: "memory")
#define CP_WAITP()  asm volatile("cp.async.wait_group %0;" :: "n"(PFD - 1) : "memory")
#define CP_WAIT0()  asm volatile("cp.async.wait_group 0;" ::: "memory")

__device__ __forceinline__ void ldsm_x4(uint32_t* r, uint32_t addr) {
    asm volatile("ldmatrix.sync.aligned.m8n8.x4.shared.b16 {%0,%1,%2,%3}, [%4];"
        : "=r"(r[0]), "=r"(r[1]), "=r"(r[2]), "=r"(r[3]) : "r"(addr));
}
__device__ __forceinline__ void ldsm_x4_t(uint32_t* r, uint32_t addr) {
    asm volatile("ldmatrix.sync.aligned.m8n8.x4.trans.shared.b16 {%0,%1,%2,%3}, [%4];"
        : "=r"(r[0]), "=r"(r[1]), "=r"(r[2]), "=r"(r[3]) : "r"(addr));
}
__device__ __forceinline__ void mma_f16(float* d, const uint32_t* a, uint32_t b0, uint32_t b1) {
    asm volatile(
        "mma.sync.aligned.m16n8k16.row.col.f32.f16.f16.f32 "
        "{%0,%1,%2,%3}, {%4,%5,%6,%7}, {%8,%9}, {%0,%1,%2,%3};"
        : "+f"(d[0]), "+f"(d[1]), "+f"(d[2]), "+f"(d[3])
        : "r"(a[0]), "r"(a[1]), "r"(a[2]), "r"(a[3]), "r"(b0), "r"(b1));
}

// ---------------- device-wide barrier (128 CTAs, 1/SM, all resident) --------
__device__ __forceinline__ void grid_barrier(unsigned target) {
    __syncthreads();
    if (threadIdx.x == 0) {
        __threadfence();
        unsigned old = atomicAdd(&g_bar_count, 1u);
        if (old == NCTA - 1) {
            atomicExch(&g_bar_count, 0u);
            __threadfence();
            atomicAdd(&g_bar_epoch, 1u);
        } else {
            unsigned e;
            do {
                asm volatile("ld.acquire.gpu.u32 %0, [%1];"
                             : "=r"(e) : "l"(&g_bar_epoch));
                if ((int)(e - target) >= 0) break;
                __nanosleep(32);
            } while (true);
        }
    }
    __syncthreads();
}

// ---------------- stage-load helpers (shared addressing) ---------------------
// A: 128 rows x BK halves; B: BK rows x 64 halves. uA/uB = stage-0 bases.
__device__ __forceinline__ void load_A_stage(uint32_t uA, const __half* A,
                                             int K, int c, int s, int tid) {
    const __half* Ag = A + c * BK;
    uint32_t aB = uA + s * A_STG_B;
    #pragma unroll
    for (int i = 0; i < 2; i++) {
        int idx = tid + i * NTHR;
        int r = idx >> 3, q = idx & 7;
        cpa16(aB + r * ASTR_B + q * 16, Ag + (long)r * K + q * 8);
    }
}
__device__ __forceinline__ void load_B_stage(uint32_t uB, const __half* B,
                                             int c, int s, int tid) {
    const __half* Bg = B + (long)(c * BK) * HDIM;
    uint32_t bB = uB + s * B_STG_B;
    int r = tid >> 3, q = tid & 7;
    cpa16(bB + r * BSTR_B + q * 16, Bg + (long)r * HDIM + q * 8);
}

// Cross-phase prefetch: issue first PFD stages of one operand, UNCOMMITTED.
// The consuming phase's first commit folds them into its group 1.
__device__ __forceinline__ void prefetch_A(char* smraw, const __half* A, int K, int tid) {
    const uint32_t uA = smem_u32(smraw + SM_BIAS_B);
    #pragma unroll
    for (int c = 0; c < PFD; c++) load_A_stage(uA, A, K, c, c, tid);
}
__device__ __forceinline__ void prefetch_B(char* smraw, const __half* B, int tid) {
    const uint32_t uB = smem_u32(smraw + SM_BIAS_B + NSTAGE * A_STG_B);
    #pragma unroll
    for (int c = 0; c < PFD; c++) load_B_stage(uB, B, c, c, tid);
}

// ---------------- fp16 mma.sync GEMM phase -----------------------------------
// C = act(oscale * (A @ B) + bias). 128x64 tile, warps 4x4, warp 32x16.
// ACT: 0 none, 1 relu, 2 tanh. MODE: 0 half out, 2 fp32 out.
// PRE: 0 none, 1 = A stages 0..PFD-1 already issued, 2 = B stages issued.
template <int ACT, int MODE, int PRE>
__device__ void gemm_phase(char* smraw,
        const __half* A, const __half* B, const float* bias,
        __half* Ch, float* Cf, int K, float oscale, int bx, int by) {
    float* sbias = (float*)smraw;
    char* sA = smraw + SM_BIAS_B;
    char* sB = sA + NSTAGE * A_STG_B;
    const uint32_t uA = smem_u32(sA);
    const uint32_t uB = smem_u32(sB);

    const int tid = threadIdx.x;
    const int wid = tid >> 5, lane = tid & 31;
    const int wm = wid >> 2, wn = wid & 3;       // 4 x 4 warps
    const int gid = lane >> 2, tig = lane & 3;
    const int l15 = lane & 15, l4 = lane >> 4;

    A += (long)(by * BM) * K;
    B += (long)bx * BN;

    if (bias && tid < BN) sbias[tid] = bias[bx * BN + tid];

    const int NC = K / BK;

    const uint32_t aLane = (uint32_t)((wm * 32 + l15) * ASTR_B + l4 * 16);
    const uint32_t bLane = (uint32_t)(l15 * BSTR_B + (wn * 16 + l4 * 8) * 2);

    float d[2][2][4] = {};

    // prologue: PFD committed groups; prefetched operand already in flight
    #pragma unroll
    for (int c = 0; c < PFD; c++) {
        if (c < NC) {
            if (PRE != 1) load_A_stage(uA, A, K, c, c, tid);
            if (PRE != 2) load_B_stage(uB, B, c, c, tid);
        }
        CP_COMMIT();
    }

    for (int c = 0; c < NC; c++) {
        CP_WAITP();
        __syncthreads();
        if (c + PFD < NC) {
            load_A_stage(uA, A, K, c + PFD, (c + PFD) % NSTAGE, tid);
            load_B_stage(uB, B, c + PFD, (c + PFD) % NSTAGE, tid);
        }
        CP_COMMIT();

        const int s = c % NSTAGE;
        const uint32_t aS = uA + s * A_STG_B + aLane;
        const uint32_t bS = uB + s * B_STG_B + bLane;

        uint32_t a0[2][4], a1[2][4], bp[2][4];
        ldsm_x4(a0[0], aS);
        ldsm_x4(a1[0], aS + 16 * ASTR_B);
        ldsm_x4_t(bp[0], bS);
        #pragma unroll
        for (int ks = 0; ks < 4; ks++) {
            const int cu = ks & 1, nx = cu ^ 1;
            if (ks < 3) {
                ldsm_x4(a0[nx], aS + (ks + 1) * 32);
                ldsm_x4(a1[nx], aS + (ks + 1) * 32 + 16 * ASTR_B);
                ldsm_x4_t(bp[nx], bS + (ks + 1) * 16 * BSTR_B);
            }
            mma_f16(d[0][0], a0[cu], bp[cu][0], bp[cu][1]);
            mma_f16(d[1][0], a1[cu], bp[cu][0], bp[cu][1]);
            mma_f16(d[0][1], a0[cu], bp[cu][2], bp[cu][3]);
            mma_f16(d[1][1], a1[cu], bp[cu][2], bp[cu][3]);
        }
    }
    CP_WAIT0();

    #pragma unroll
    for (int mt = 0; mt < 2; mt++) {
        #pragma unroll
        for (int hf = 0; hf < 2; hf++) {
            const long row = (long)by * BM + wm * 32 + mt * 16 + hf * 8 + gid;
            const long rc = row * HDIM + bx * BN;
            #pragma unroll
            for (int nt = 0; nt < 2; nt++) {
                const int cl = wn * 16 + nt * 8 + 2 * tig;
                float v0 = d[mt][nt][hf * 2 + 0] * oscale;
                float v1 = d[mt][nt][hf * 2 + 1] * oscale;
                if (bias) { v0 += sbias[cl]; v1 += sbias[cl + 1]; }
                if (ACT == 1) { v0 = fmaxf(v0, 0.0f); v1 = fmaxf(v1, 0.0f); }
                if (ACT == 2) { v0 = tanhf(v0); v1 = tanhf(v1); }
                if (MODE == 0)
                    *(__half2*)(Ch + rc + cl) = __floats2half2_rn(v0, v1);
                else
                    *(float2*)(Cf + rc + cl) = make_float2(v0, v1);
            }
        }
    }
}

// ---------------- the megakernel --------------------------------------------
#define TOT4_A (G * NNODE * NNODE / 4)
#define TOT4_X (G * NNODE * FDIM / 4)
#define TOT4_W ((1 + LAYERS) * HDIM * HDIM / 4)
#define TOT4_WIN (FDIM * HDIM / 4)
#define A_SLICE (TOT4_A / NCTA)               // 8192 float4 per CTA

__global__ void __launch_bounds__(NTHR, 1)
meganet(const float* batch_xs, const float* batch_as,
        const float* w_in, const float* b_in,
        const float* gcn_w, const float* gcn_b,
        const int* gidx, const int* mask, float* out) {
    extern __shared__ char smraw[];
    const int cta = blockIdx.x;
    const int tid = threadIdx.x;
    unsigned bt = g_bar_epoch;

    // decompositions (fixed per CTA)
    const int d_bx = cta & 3,  d_by = cta >> 2;               // dense: 4 x 32
    const int x_bx = cta & 3,  x_by = (cta >> 2) & 7, x_g = cta >> 5;  // ax: 4x8x4
    const __half* Abase = g_ah + (long)x_g * NNODE * NNODE;

    // ---- phase P: convert X + W ----
    {
        const float4* x4 = (const float4*)batch_xs;
        const float4* wi = (const float4*)w_in;
        const float4* gw = (const float4*)gcn_w;
        __half2* xh2 = (__half2*)g_xin;
        __half2* wh2 = (__half2*)g_wh;
        const int total = TOT4_X + TOT4_W;
        for (int i = cta * NTHR + tid; i < total; i += NCTA * NTHR) {
            float4 v; __half2* dst;
            if (i < TOT4_X) { v = x4[i]; dst = xh2 + 2 * i; }
            else {
                int j = i - TOT4_X;
                if (j < TOT4_WIN) { v = wi[j]; dst = wh2 + 2 * j; }
                else { v = gw[j - TOT4_WIN]; dst = wh2 + 2 * j; }
            }
            dst[0] = __floats2half2_rn(v.x, v.y);
            dst[1] = __floats2half2_rn(v.z, v.w);
        }
    }
    grid_barrier(++bt);

    // ---- phase 0: h0 = relu(X @ w_in + b), then convert A slice ----
    gemm_phase<1, 0, 0>(smraw, g_xin, g_wh, b_in, g_h0h, nullptr,
                        FDIM, 1.0f, d_bx, d_by);
    {
        const float4* a4 = (const float4*)batch_as + (long)cta * A_SLICE;
        __half2* ah2 = (__half2*)g_ah + (long)cta * A_SLICE * 2;
        #pragma unroll 4
        for (int i = tid; i < A_SLICE; i += NTHR) {
            float4 v = a4[i];
            ah2[2 * i + 0] = __floats2half2_rn(v.x * 1024.0f, v.y * 1024.0f);
            ah2[2 * i + 1] = __floats2half2_rn(v.z * 1024.0f, v.w * 1024.0f);
        }
    }
    grid_barrier(++bt);

    const float inv1024 = 1.0f / 1024.0f;
    const __half* cur = g_h0h;
    for (int i = 0; i < LAYERS; i++) {
        // ---- ax: t[g] = A[g] @ x[g] (4 bx x 8 by x 4 g) ----
        if (i == 0) {
            gemm_phase<0, 0, 0>(smraw, Abase, cur + (long)x_g * NNODE * HDIM,
                                nullptr, g_th + (long)x_g * NNODE * HDIM, nullptr,
                                NNODE, inv1024, x_bx, x_by);
        } else {
            gemm_phase<0, 0, 1>(smraw, Abase, cur + (long)x_g * NNODE * HDIM,
                                nullptr, g_th + (long)x_g * NNODE * HDIM, nullptr,
                                NNODE, inv1024, x_bx, x_by);
        }
        // prefetch this layer's dense W stages (weights stable since phase P)
        prefetch_B(smraw, g_wh + (size_t)(1 + i) * HDIM * HDIM + d_bx * BN, tid);
        grid_barrier(++bt);

        // ---- dense: x = act(t @ W_i + b_i) (4 bx x 32 by), W prefetched ----
        if (i < LAYERS - 1) {
            gemm_phase<1, 0, 2>(smraw, g_th, g_wh + (size_t)(1 + i) * HDIM * HDIM,
                                gcn_b + i * HDIM, g_xh, nullptr,
                                HDIM, 1.0f, d_bx, d_by);
            cur = g_xh;
            // prefetch next layer's adjacency A stages (stable since phase 0)
            prefetch_A(smraw, Abase + (long)(x_by * BM) * NNODE, NNODE, tid);
        } else {
            gemm_phase<2, 2, 2>(smraw, g_th, g_wh + (size_t)LAYERS * HDIM * HDIM,
                                gcn_b + (LAYERS - 1) * HDIM, nullptr, g_xl,
                                HDIM, 1.0f, d_bx, d_by);
        }
        grid_barrier(++bt);
    }

    // ---- phase R1: partial masked sums ----
    {
        const int b = cta >> 2;
        const int s = ((cta & 3) << 1) + (tid >> 8);
        const int h = tid & 255;
        const int g = gidx[b];
        const float* xb = g_xl  + (size_t)g * NNODE * HDIM;
        const __half* rb = g_h0h + (size_t)g * NNODE * HDIM;
        const int* mb = mask + b * NNODE;
        float acc = 0.0f, cnt = 0.0f;
        #pragma unroll 4
        for (int n = s * 128; n < s * 128 + 128; n++) {
            float m = (mb[n] != 0) ? 1.0f : 0.0f;
            cnt += m;
            acc += m * (xb[(size_t)n * HDIM + h] +
                        __half2float(rb[(size_t)n * HDIM + h]));
        }
        g_part[(b * 8 + s) * HDIM + h] = acc;
        if (h == 0) g_cnt[b * 8 + s] = cnt;
    }
    grid_barrier(++bt);

    // ---- phase R2: combine (32 CTAs, first 256 threads) ----
    if (cta < BATCH && tid < HDIM) {
        const int b = cta, h = tid;
        float acc = 0.0f, cnt = 0.0f;
        #pragma unroll
        for (int s = 0; s < 8; s++) {
            acc += g_part[(b * 8 + s) * HDIM + h];
            cnt += g_cnt[b * 8 + s];
        }
        out[b * HDIM + h] = acc / fmaxf(cnt, 1.0f);
    }
}

// ---------------- launch -----------------------------------------------------
extern "C" void kernel_launch(void* const* d_in, const int* in_sizes, int n_in,
                              void* d_out, int out_size) {
    const float* batch_xs = (const float*)d_in[0];
    const float* batch_as = (const float*)d_in[1];
    const float* w_in     = (const float*)d_in[2];
    const float* b_in     = (const float*)d_in[3];
    const float* gcn_w    = (const float*)d_in[4];
    const float* gcn_b    = (const float*)d_in[5];
    const int*   gidx     = (const int*)d_in[6];
    const int*   cp_mask  = (const int*)d_in[7];
    float* out = (float*)d_out;

    cudaFuncSetAttribute(meganet, cudaFuncAttributeMaxDynamicSharedMemorySize,
                         SMEM_BYTES);

    meganet<<<NCTA, NTHR, SMEM_BYTES>>>(batch_xs, batch_as, w_in, b_in,
                                        gcn_w, gcn_b, gidx, cp_mask, out);
}

// round 16
// speedup vs baseline: 1.0946x; 1.0663x over previous
#include <cuda_runtime.h>
#include <cuda_fp16.h>
#include <math.h>
#include <stdint.h>

#define G 4
#define NNODE 1024
#define FDIM 256
#define HDIM 256
#define BATCH 32
#define LAYERS 4
#define NCTA 128
#define NTHR 512

// ---------------- scratch (device globals; no allocation allowed) -----------
__device__ __half g_ah [G * NNODE * NNODE];          // adjacency, half, x1024
__device__ __half g_xin[G * NNODE * FDIM];           // input feats, half
__device__ __half g_wh [(1 + LAYERS) * HDIM * HDIM]; // weights, half
__device__ __half g_h0h[G * NNODE * HDIM];           // h0 half (residual + layer0 in)
__device__ __half g_th [G * NNODE * HDIM];           // A @ x (half)
__device__ __half g_xh [G * NNODE * HDIM];           // hidden activations (half)
__device__ __half g_xs [G * NNODE * HDIM];           // tanh(z) + h0  (half)
__device__ float  g_part[BATCH * 8 * HDIM];          // reduce partials
__device__ float  g_cnt [BATCH * 8];                 // reduce counts
__device__ unsigned g_bar_epoch;                     // barrier epoch (monotone)
__device__ unsigned g_bar_count;                     // barrier arrive counter

// ---------------- tiling (R10 champion config) -------------------------------
// CTA tile 128(M) x 64(N), warps 4(M) x 4(N), warp tile 32x16. 1 CTA/SM.
#define BM 128
#define BN 64
#define BK 64
#define NSTAGE 4
#define PFD 3
#define ASTR_B 144                        // A chunk row stride bytes
#define BSTR_B 144                        // B chunk row stride bytes
#define A_STG_B (BM * ASTR_B)             // 18432 B
#define B_STG_B (BK * BSTR_B)             // 9216 B
#define SM_BIAS_B 512
#define SMEM_BYTES (SM_BIAS_B + NSTAGE * (A_STG_B + B_STG_B))   // 111104 B

__device__ __forceinline__ uint32_t smem_u32(const void* p) {
    uint32_t a;
    asm("{ .reg .u64 t; cvta.to.shared.u64 t, %1; cvt.u32.u64 %0, t; }" : "=r"(a) : "l"(p));
    return a;
}
__device__ __forceinline__ void cpa16(uint32_t dst, const void* src) {
    asm volatile("cp.async.cg.shared.global [%0], [%1], 16;" :: "r"(dst), "l"(src));
}
#define CP_COMMIT() asm volatile("cp.async.commit_group;" ::: "memory")
#define CP_WAITP()  asm volatile("cp.async.wait_group %0;" :: "n"(PFD - 1) : "memory")
#define CP_WAIT0()  asm volatile("cp.async.wait_group 0;" ::: "memory")

__device__ __forceinline__ void ldsm_x4(uint32_t* r, uint32_t addr) {
    asm volatile("ldmatrix.sync.aligned.m8n8.x4.shared.b16 {%0,%1,%2,%3}, [%4];"
        : "=r"(r[0]), "=r"(r[1]), "=r"(r[2]), "=r"(r[3]) : "r"(addr));
}
__device__ __forceinline__ void ldsm_x4_t(uint32_t* r, uint32_t addr) {
    asm volatile("ldmatrix.sync.aligned.m8n8.x4.trans.shared.b16 {%0,%1,%2,%3}, [%4];"
        : "=r"(r[0]), "=r"(r[1]), "=r"(r[2]), "=r"(r[3]) : "r"(addr));
}
__device__ __forceinline__ void mma_f16(float* d, const uint32_t* a, uint32_t b0, uint32_t b1) {
    asm volatile(
        "mma.sync.aligned.m16n8k16.row.col.f32.f16.f16.f32 "
        "{%0,%1,%2,%3}, {%4,%5,%6,%7}, {%8,%9}, {%0,%1,%2,%3};"
        : "+f"(d[0]), "+f"(d[1]), "+f"(d[2]), "+f"(d[3])
        : "r"(a[0]), "r"(a[1]), "r"(a[2]), "r"(a[3]), "r"(b0), "r"(b1));
}

// ---------------- device-wide barrier (128 CTAs, 1/SM, all resident) --------
__device__ __forceinline__ void grid_barrier(unsigned target) {
    __syncthreads();
    if (threadIdx.x == 0) {
        __threadfence();
        unsigned old = atomicAdd(&g_bar_count, 1u);
        if (old == NCTA - 1) {
            atomicExch(&g_bar_count, 0u);
            __threadfence();
            atomicAdd(&g_bar_epoch, 1u);
        } else {
            unsigned e;
            do {
                asm volatile("ld.acquire.gpu.u32 %0, [%1];"
                             : "=r"(e) : "l"(&g_bar_epoch));
                if ((int)(e - target) >= 0) break;
                __nanosleep(32);
            } while (true);
        }
    }
    __syncthreads();
}

// ---------------- fp16 mma.sync GEMM phase -----------------------------------
// C = act(oscale * (A @ B) + bias). 128x64 tile, warp grid 4(M) x 4(N),
// warp tile 32x16. ACT: 0 none, 1 relu, 2 tanh.
// MODE: 0 half out; 3 = tanh + residual(Res) added, half out.
template <int ACT, int MODE>
__device__ void gemm_phase(char* smraw,
        const __half* A, const __half* B, const float* bias,
        __half* Ch, const __half* Res, int K, float oscale, int bx, int by) {
    float* sbias = (float*)smraw;
    char* sA = smraw + SM_BIAS_B;
    char* sB = sA + NSTAGE * A_STG_B;
    const uint32_t uA = smem_u32(sA);
    const uint32_t uB = smem_u32(sB);

    const int tid = threadIdx.x;
    const int wid = tid >> 5, lane = tid & 31;
    const int wm = wid >> 2, wn = wid & 3;       // 4 x 4 warps
    const int gid = lane >> 2, tig = lane & 3;
    const int l15 = lane & 15, l4 = lane >> 4;

    A += (long)(by * BM) * K;
    B += (long)bx * BN;

    if (bias && tid < BN) sbias[tid] = bias[bx * BN + tid];

    const int NC = K / BK;

    auto load_stage = [&](int c, int s) {
        const __half* Ag = A + c * BK;
        const __half* Bg = B + (long)(c * BK) * HDIM;
        uint32_t aB = uA + s * A_STG_B;
        uint32_t bB = uB + s * B_STG_B;
        #pragma unroll
        for (int i = 0; i < 2; i++) {            // A: 128 rows x 8 x 16B
            int idx = tid + i * NTHR;
            int r = idx >> 3, q = idx & 7;
            cpa16(aB + r * ASTR_B + q * 16, Ag + (long)r * K + q * 8);
        }
        {                                        // B: 64 rows x 8 x 16B
            int r = tid >> 3, q = tid & 7;
            cpa16(bB + r * BSTR_B + q * 16, Bg + (long)r * HDIM + q * 8);
        }
    };

    const uint32_t aLane = (uint32_t)((wm * 32 + l15) * ASTR_B + l4 * 16);
    const uint32_t bLane = (uint32_t)(l15 * BSTR_B + (wn * 16 + l4 * 8) * 2);

    float d[2][2][4] = {};

    #pragma unroll
    for (int c = 0; c < PFD; c++) {
        if (c < NC) load_stage(c, c);
        CP_COMMIT();
    }

    for (int c = 0; c < NC; c++) {
        CP_WAITP();
        __syncthreads();
        if (c + PFD < NC) load_stage(c + PFD, (c + PFD) % NSTAGE);
        CP_COMMIT();

        const int s = c % NSTAGE;
        const uint32_t aS = uA + s * A_STG_B + aLane;
        const uint32_t bS = uB + s * B_STG_B + bLane;

        uint32_t a0[2][4], a1[2][4], bp[2][4];
        ldsm_x4(a0[0], aS);
        ldsm_x4(a1[0], aS + 16 * ASTR_B);
        ldsm_x4_t(bp[0], bS);
        #pragma unroll
        for (int ks = 0; ks < 4; ks++) {
            const int cu = ks & 1, nx = cu ^ 1;
            if (ks < 3) {
                ldsm_x4(a0[nx], aS + (ks + 1) * 32);
                ldsm_x4(a1[nx], aS + (ks + 1) * 32 + 16 * ASTR_B);
                ldsm_x4_t(bp[nx], bS + (ks + 1) * 16 * BSTR_B);
            }
            mma_f16(d[0][0], a0[cu], bp[cu][0], bp[cu][1]);
            mma_f16(d[1][0], a1[cu], bp[cu][0], bp[cu][1]);
            mma_f16(d[0][1], a0[cu], bp[cu][2], bp[cu][3]);
            mma_f16(d[1][1], a1[cu], bp[cu][2], bp[cu][3]);
        }
    }
    CP_WAIT0();

    #pragma unroll
    for (int mt = 0; mt < 2; mt++) {
        #pragma unroll
        for (int hf = 0; hf < 2; hf++) {
            const long row = (long)by * BM + wm * 32 + mt * 16 + hf * 8 + gid;
            const long rc = row * HDIM + bx * BN;
            #pragma unroll
            for (int nt = 0; nt < 2; nt++) {
                const int cl = wn * 16 + nt * 8 + 2 * tig;
                float v0 = d[mt][nt][hf * 2 + 0] * oscale;
                float v1 = d[mt][nt][hf * 2 + 1] * oscale;
                if (bias) { v0 += sbias[cl]; v1 += sbias[cl + 1]; }
                if (ACT == 1) { v0 = fmaxf(v0, 0.0f); v1 = fmaxf(v1, 0.0f); }
                if (ACT == 2) { v0 = tanhf(v0); v1 = tanhf(v1); }
                if (MODE == 3) {
                    __half2 r2 = *(const __half2*)(Res + rc + cl);
                    float2 rf = __half22float2(r2);
                    v0 += rf.x; v1 += rf.y;
                }
                *(__half2*)(Ch + rc + cl) = __floats2half2_rn(v0, v1);
            }
        }
    }
}

// ---------------- the megakernel --------------------------------------------
#define TOT4_A (G * NNODE * NNODE / 4)
#define TOT4_X (G * NNODE * FDIM / 4)
#define TOT4_W ((1 + LAYERS) * HDIM * HDIM / 4)
#define TOT4_WIN (FDIM * HDIM / 4)
#define A_SLICE (TOT4_A / NCTA)               // 8192 float4 per CTA

__global__ void __launch_bounds__(NTHR, 1)
meganet(const float* batch_xs, const float* batch_as,
        const float* w_in, const float* b_in,
        const float* gcn_w, const float* gcn_b,
        const int* gidx, const int* mask, float* out) {
    extern __shared__ char smraw[];
    const int cta = blockIdx.x;
    const int tid = threadIdx.x;
    unsigned bt = g_bar_epoch;                // epoch snapshot

    // ---- phase P: convert X + W (A overlapped with dense phase) ----
    {
        const float4* x4 = (const float4*)batch_xs;
        const float4* wi = (const float4*)w_in;
        const float4* gw = (const float4*)gcn_w;
        __half2* xh2 = (__half2*)g_xin;
        __half2* wh2 = (__half2*)g_wh;
        const int total = TOT4_X + TOT4_W;
        for (int i = cta * NTHR + tid; i < total; i += NCTA * NTHR) {
            float4 v; __half2* dst;
            if (i < TOT4_X) { v = x4[i]; dst = xh2 + 2 * i; }
            else {
                int j = i - TOT4_X;
                if (j < TOT4_WIN) { v = wi[j]; dst = wh2 + 2 * j; }
                else { v = gw[j - TOT4_WIN]; dst = wh2 + 2 * j; }
            }
            dst[0] = __floats2half2_rn(v.x, v.y);
            dst[1] = __floats2half2_rn(v.z, v.w);
        }
    }
    grid_barrier(++bt);

    // ---- phase 0: h0 = relu(X @ w_in + b) (4 bx x 32 by), then convert
    //      this CTA's A slice (overlaps other CTAs' GEMM compute) ----
    gemm_phase<1, 0>(smraw, g_xin, g_wh, b_in, g_h0h, nullptr,
                     FDIM, 1.0f, cta & 3, cta >> 2);
    {
        const float4* a4 = (const float4*)batch_as + (long)cta * A_SLICE;
        __half2* ah2 = (__half2*)g_ah + (long)cta * A_SLICE * 2;
        #pragma unroll 4
        for (int i = tid; i < A_SLICE; i += NTHR) {
            float4 v = a4[i];
            ah2[2 * i + 0] = __floats2half2_rn(v.x * 1024.0f, v.y * 1024.0f);
            ah2[2 * i + 1] = __floats2half2_rn(v.z * 1024.0f, v.w * 1024.0f);
        }
    }
    grid_barrier(++bt);

    const float inv1024 = 1.0f / 1024.0f;
    const __half* cur = g_h0h;
    for (int i = 0; i < LAYERS; i++) {
        // t[g] = A[g] @ x[g]   (4 bx x 8 by x 4 g = 128 tiles)
        {
            const int bx = cta & 3, by = (cta >> 2) & 7, bz = cta >> 5;
            gemm_phase<0, 0>(smraw,
                g_ah + (long)bz * NNODE * NNODE,
                cur + (long)bz * NNODE * HDIM, nullptr,
                g_th + (long)bz * NNODE * HDIM, nullptr,
                NNODE, inv1024, bx, by);
        }
        grid_barrier(++bt);
        // x = act(t @ W_i + b_i)  (4 bx x 32 by)
        if (i < LAYERS - 1) {
            gemm_phase<1, 0>(smraw, g_th, g_wh + (size_t)(1 + i) * HDIM * HDIM,
                             gcn_b + i * HDIM, g_xh, nullptr,
                             HDIM, 1.0f, cta & 3, cta >> 2);
            cur = g_xh;
        } else {
            // final: xs = tanh(t @ W + b) + h0, stored half
            gemm_phase<2, 3>(smraw, g_th, g_wh + (size_t)LAYERS * HDIM * HDIM,
                             gcn_b + (LAYERS - 1) * HDIM, g_xs, g_h0h,
                             HDIM, 1.0f, cta & 3, cta >> 2);
        }
        grid_barrier(++bt);
    }

    // ---- phase R1: partial masked sums over xs (single half stream)
    //      128 CTAs x 512 thr: b = cta>>2, s = (cta&3)*2 + (tid>>8),
    //      h = tid & 255; each slice covers 128 nodes ----
    {
        const int b = cta >> 2;
        const int s = ((cta & 3) << 1) + (tid >> 8);
        const int h = tid & 255;
        const int g = gidx[b];
        const __half* xb = g_xs + (size_t)g * NNODE * HDIM;
        const int* mb = mask + b * NNODE;
        float acc = 0.0f, cnt = 0.0f;
        #pragma unroll 8
        for (int n = s * 128; n < s * 128 + 128; n++) {
            float m = (mb[n] != 0) ? 1.0f : 0.0f;
            cnt += m;
            acc += m * __half2float(xb[(size_t)n * HDIM + h]);
        }
        g_part[(b * 8 + s) * HDIM + h] = acc;
        if (h == 0) g_cnt[b * 8 + s] = cnt;
    }
    grid_barrier(++bt);

    // ---- phase R2: combine (32 CTAs, first 256 threads) ----
    if (cta < BATCH && tid < HDIM) {
        const int b = cta, h = tid;
        float acc = 0.0f, cnt = 0.0f;
        #pragma unroll
        for (int s = 0; s < 8; s++) {
            acc += g_part[(b * 8 + s) * HDIM + h];
            cnt += g_cnt[b * 8 + s];
        }
        out[b * HDIM + h] = acc / fmaxf(cnt, 1.0f);
    }
}

// ---------------- launch -----------------------------------------------------
extern "C" void kernel_launch(void* const* d_in, const int* in_sizes, int n_in,
                              void* d_out, int out_size) {
    const float* batch_xs = (const float*)d_in[0];
    const float* batch_as = (const float*)d_in[1];
    const float* w_in     = (const float*)d_in[2];
    const float* b_in     = (const float*)d_in[3];
    const float* gcn_w    = (const float*)d_in[4];
    const float* gcn_b    = (const float*)d_in[5];
    const int*   gidx     = (const int*)d_in[6];
    const int*   cp_mask  = (const int*)d_in[7];
    float* out = (float*)d_out;

    cudaFuncSetAttribute(meganet, cudaFuncAttributeMaxDynamicSharedMemorySize,
                         SMEM_BYTES);

    meganet<<<NCTA, NTHR, SMEM_BYTES>>>(batch_xs, batch_as, w_in, b_in,
                                        gcn_w, gcn_b, gidx, cp_mask, out);
}